// round 2
// baseline (speedup 1.0000x reference)
#include <cuda_runtime.h>
#include <math.h>

#define SEQ 14
#define HID 128
#define FEAT 13
#define THREADS 256
#define HPAD 132
#define NSEQ_TOTAL 2048
#define NBLOCKS ((NSEQ_TOTAL + SEQ - 1) / SEQ)
#define STEPS 128

typedef unsigned long long u64;

__device__ __forceinline__ u64 pk2(float lo, float hi){
    u64 r; asm("mov.b64 %0, {%1,%2};" : "=l"(r) : "f"(lo), "f"(hi)); return r;
}
__device__ __forceinline__ void upk2(float& lo, float& hi, u64 v){
    asm("mov.b64 {%0,%1}, %2;" : "=f"(lo), "=f"(hi) : "l"(v));
}
// packed dual fp32 FMA: d.lo += a.lo*b.lo ; d.hi += a.hi*b.hi  (IEEE fma, 2x FFMA rate)
__device__ __forceinline__ void fma2(u64& d, u64 a, u64 b){
    asm("fma.rn.f32x2 %0, %1, %2, %0;" : "+l"(d) : "l"(a), "l"(b));
}

__device__ __forceinline__ float fsigmoid(float x){
    float e = __expf(-x);                       // MUFU.EX2 based, ~2ulp
    return __fdividef(1.0f, 1.0f + e);          // safe: e=inf -> 0
}
__device__ __forceinline__ float ftanh(float x){
    float a = fabsf(x);
    float e = __expf(-2.0f * a);                // in (0,1], never inf
    float r = (1.0f - e) * __fdividef(1.0f, 1.0f + e);
    return copysignf(r, x);
}

__global__ __launch_bounds__(THREADS, 1)
void lstm_ed_kernel(const float* __restrict__ X, const float* __restrict__ W_ih,
                    const float* __restrict__ W_hh, const float* __restrict__ b_ih,
                    const float* __restrict__ b_hh, const float* __restrict__ W_fc,
                    const float* __restrict__ b_fc, float* __restrict__ out)
{
    __shared__ float h_sm[SEQ][HPAD];     // hidden state, padded rows (bank spread)
    __shared__ float sf_sm[SEQ][HID];     // sigmoid(f-gate)
    __shared__ float so_sm[SEQ][HID];     // sigmoid(o-gate)
    __shared__ float x_sm[SEQ][16];       // current input, zero-padded to 16
    __shared__ float wfc_sm[FEAT][HPAD];  // decoder projection weights
    __shared__ float bfc_sm[FEAT];

    const int t  = threadIdx.x;
    const int n0 = blockIdx.x * SEQ;
    const int nseq = min(SEQ, NSEQ_TOTAL - n0);
    const int j0 = t;          // rows [0,256): i-gates (t<128) / f-gates (t>=128)
    const int j1 = t + 256;    // rows [256,512): g-gates (t<128) / o-gates (t>=128)

    for (int i = t; i < SEQ*HPAD; i += THREADS) (&h_sm[0][0])[i] = 0.0f;
    for (int i = t; i < SEQ*16;   i += THREADS) (&x_sm[0][0])[i] = 0.0f;
    for (int i = t; i < FEAT*HID; i += THREADS) wfc_sm[i/HID][i%HID] = W_fc[i];
    if (t < FEAT) bfc_sm[t] = b_fc[t];

    // per-thread constant weights: W_ih rows packed for f32x2, bias
    float w0tmp[16], w1tmp[16];
    #pragma unroll
    for (int f = 0; f < 16; f++){
        w0tmp[f] = (f < FEAT) ? W_ih[j0*FEAT + f] : 0.0f;
        w1tmp[f] = (f < FEAT) ? W_ih[j1*FEAT + f] : 0.0f;
    }
    u64 wihp0[8], wihp1[8];
    #pragma unroll
    for (int p = 0; p < 8; p++){
        wihp0[p] = pk2(w0tmp[2*p], w0tmp[2*p+1]);
        wihp1[p] = pk2(w1tmp[2*p], w1tmp[2*p+1]);
    }
    const float bias0 = b_ih[j0] + b_hh[j0];
    const float bias1 = b_ih[j1] + b_hh[j1];

    const float4* w0q = reinterpret_cast<const float4*>(W_hh + (size_t)j0 * HID);
    const float4* w1q = reinterpret_cast<const float4*>(W_hh + (size_t)j1 * HID);

    float c_reg[SEQ];                     // cell state lives in reader threads (t<128)
    #pragma unroll
    for (int s = 0; s < SEQ; s++) c_reg[s] = 0.0f;

    __syncthreads();

    auto lstm_step = [&]() {
        u64 acc0[SEQ], acc1[SEQ];         // .lo = even-k partial, .hi = odd-k partial
        #pragma unroll
        for (int s = 0; s < SEQ; s++){ acc0[s] = pk2(bias0, 0.0f); acc1[s] = pk2(bias1, 0.0f); }

        // input contribution: x @ W_ih^T (K=16 incl. zero pad), weights in regs
        #pragma unroll
        for (int p = 0; p < 8; p++){
            #pragma unroll
            for (int s = 0; s < SEQ; s++){
                u64 xv = *reinterpret_cast<const u64*>(&x_sm[s][2*p]);
                fma2(acc0[s], wihp0[p], xv);
                fma2(acc1[s], wihp1[p], xv);
            }
        }
        // hidden contribution: h @ W_hh^T, W rows L1-resident, h broadcast from smem
        #pragma unroll 4
        for (int kq = 0; kq < 32; kq++){
            float4 w0 = __ldg(&w0q[kq]);
            float4 w1 = __ldg(&w1q[kq]);
            u64 w0a = pk2(w0.x, w0.y), w0b = pk2(w0.z, w0.w);
            u64 w1a = pk2(w1.x, w1.y), w1b = pk2(w1.z, w1.w);
            #pragma unroll
            for (int s = 0; s < SEQ; s++){
                const u64* hp = reinterpret_cast<const u64*>(&h_sm[s][kq*4]);
                u64 ha = hp[0], hb = hp[1];
                fma2(acc0[s], w0a, ha);
                fma2(acc0[s], w0b, hb);
                fma2(acc1[s], w1a, ha);
                fma2(acc1[s], w1b, hb);
            }
        }
        // threads t>=128 own f/o gates: publish sigmoid(f), sigmoid(o)
        if (t >= 128){
            const int k = t - 128;
            #pragma unroll
            for (int s = 0; s < SEQ; s++){
                float lo, hi;
                upk2(lo, hi, acc0[s]); sf_sm[s][k] = fsigmoid(lo + hi);
                upk2(lo, hi, acc1[s]); so_sm[s][k] = fsigmoid(lo + hi);
            }
        }
        __syncthreads();
        // threads t<128 own i/g gates + the cell update for hidden unit k=t
        if (t < 128){
            const int k = t;
            #pragma unroll
            for (int s = 0; s < SEQ; s++){
                float lo, hi;
                upk2(lo, hi, acc0[s]); float iv = fsigmoid(lo + hi);
                upk2(lo, hi, acc1[s]); float gv = ftanh(lo + hi);
                float cn = fmaf(sf_sm[s][k], c_reg[s], iv * gv);
                c_reg[s] = cn;
                h_sm[s][k] = so_sm[s][k] * ftanh(cn);
            }
        }
        __syncthreads();
    };

    // ---------------- encoder ----------------
    for (int step = 0; step < STEPS; step++){
        if (t < nseq * FEAT){
            int s = t / FEAT, f = t - s * FEAT;
            x_sm[s][f] = X[(size_t)(n0 + s) * (STEPS * FEAT) + step * FEAT + f];
        }
        __syncthreads();
        lstm_step();
    }

    // embeddings = final h  -> out[0 : 2048*128)
    for (int i = t; i < nseq * HID; i += THREADS){
        int s = i >> 7, k = i & (HID - 1);
        out[(size_t)(n0 + s) * HID + k] = h_sm[s][k];
    }

    // ---------------- decoder ----------------
    // x_sm still holds X[:, 127, :] == x0 (reference uses last input frame)
    float* dec_out = out + (size_t)NSEQ_TOTAL * HID;
    for (int step = 0; step < STEPS; step++){
        lstm_step();
        if (t < nseq * FEAT){
            int s = t / FEAT, f = t - s * FEAT;
            u64 a0 = pk2(bfc_sm[f], 0.0f), a1 = pk2(0.0f, 0.0f);
            const u64* wr = reinterpret_cast<const u64*>(&wfc_sm[f][0]);
            const u64* hr = reinterpret_cast<const u64*>(&h_sm[s][0]);
            #pragma unroll
            for (int k2 = 0; k2 < 64; k2 += 2){
                fma2(a0, wr[k2],   hr[k2]);
                fma2(a1, wr[k2+1], hr[k2+1]);
            }
            float l0, h0v, l1, h1v; upk2(l0, h0v, a0); upk2(l1, h1v, a1);
            float o = (l0 + h0v) + (l1 + h1v);
            dec_out[((size_t)(n0 + s) * STEPS + step) * FEAT + f] = o;
            x_sm[s][f] = o;   // feedback: next decoder input
        }
        __syncthreads();
    }
}

extern "C" void kernel_launch(void* const* d_in, const int* in_sizes, int n_in,
                              void* d_out, int out_size)
{
    const float* X    = (const float*)d_in[0];
    const float* W_ih = (const float*)d_in[1];
    const float* W_hh = (const float*)d_in[2];
    const float* b_ih = (const float*)d_in[3];
    const float* b_hh = (const float*)d_in[4];
    const float* W_fc = (const float*)d_in[5];
    const float* b_fc = (const float*)d_in[6];
    lstm_ed_kernel<<<NBLOCKS, THREADS>>>(X, W_ih, W_hh, b_ih, b_hh, W_fc, b_fc, (float*)d_out);
}